// round 13
// baseline (speedup 1.0000x reference)
#include <cuda_runtime.h>
#include <cuda_fp16.h>
#include <math.h>
#include <stdint.h>

#define BDIM 64
#define SDIM 2048
#define IDIM 512
#define HDIM 512
#define BSCALE 512.0f
#define INV_BSCALE (1.0f / 512.0f)

// ---------------- device scratch (no cudaMalloc allowed) -------------------
__device__ float g_hb[BDIM * HDIM];
__device__ float g_att[BDIM * SDIM];
__device__ float g_cbar[BDIM * IDIM];
__device__ int   g_mask_is_byte;

__device__ __half          g_ctx16[BDIM * SDIM * IDIM];   // fp16(ctx)
__device__ unsigned short  g_ctxp [BDIM * SDIM * IDIM];   // [e5m2(aL), e5m2(aH)]
__device__ __half          g_wc16 [HDIM * IDIM];          // fp16(512*Wc)
__device__ unsigned short  g_wcp  [HDIM * IDIM];          // [e5m2(bH'), e5m2(bL')]

// ---------------- PTX helpers (sm_80/89-level only) --------------------------
__device__ __forceinline__ uint32_t smem_u32(const void* p) {
    uint32_t a;
    asm("{ .reg .u64 t; cvta.to.shared.u64 t, %1; cvt.u32.u64 %0, t; }" : "=r"(a) : "l"(p));
    return a;
}
#define CP16(dst, src) asm volatile("cp.async.cg.shared.global [%0], [%1], 16;" :: "r"(dst), "l"(src))
#define CP_COMMIT()    asm volatile("cp.async.commit_group;" ::: "memory")
#define CP_WAIT(n)     asm volatile("cp.async.wait_group %0;" :: "n"(n) : "memory")

#define LDSM4(r, a)                                                           \
    asm volatile("ldmatrix.sync.aligned.m8n8.x4.shared.b16 {%0,%1,%2,%3}, [%4];" \
        : "=r"((r)[0]), "=r"((r)[1]), "=r"((r)[2]), "=r"((r)[3]) : "r"(a))

#define MMA_F16(c, a, b0, b1)                                                 \
    asm volatile("mma.sync.aligned.m16n8k16.row.col.f32.f16.f16.f32 "         \
        "{%0,%1,%2,%3},{%4,%5,%6,%7},{%8,%9},{%0,%1,%2,%3};"                  \
        : "+f"((c)[0]), "+f"((c)[1]), "+f"((c)[2]), "+f"((c)[3])              \
        : "r"((a)[0]), "r"((a)[1]), "r"((a)[2]), "r"((a)[3]), "r"(b0), "r"(b1))

#define MMA_E5(c, a, b0, b1)                                                  \
    asm volatile("mma.sync.aligned.m16n8k32.row.col.f32.e5m2.e5m2.f32 "       \
        "{%0,%1,%2,%3},{%4,%5,%6,%7},{%8,%9},{%0,%1,%2,%3};"                  \
        : "+f"((c)[0]), "+f"((c)[1]), "+f"((c)[2]), "+f"((c)[3])              \
        : "r"((a)[0]), "r"((a)[1]), "r"((a)[2]), "r"((a)[3]), "r"(b0), "r"(b1))

// pack two floats into 2 e5m2 bytes: byte0 = e5m2(lo), byte1 = e5m2(hi)
__device__ __forceinline__ unsigned short pack_e5m2(float hi, float lo) {
    unsigned short d;
    asm("cvt.rn.satfinite.e5m2x2.f32 %0, %1, %2;" : "=h"(d) : "f"(hi), "f"(lo));
    return d;
}

#define SWZ8(r) ((uint32_t)((((r) & 3) ^ (((r) >> 2) & 1)) << 4))

// ---------------------------------------------------------------------------
// K0: detect mask storage (int32 vs uint8)
// ---------------------------------------------------------------------------
__global__ void k0_detect(const unsigned char* __restrict__ mraw) {
    __shared__ int found;
    if (threadIdx.x == 0) found = 0;
    __syncthreads();
    int acc = 0;
    for (int i = threadIdx.x; i < 4096; i += 256)
        if ((i & 3) != 0 && mraw[i] != 0) acc = 1;
    if (acc) atomicOr(&found, 1);
    __syncthreads();
    if (threadIdx.x == 0) g_mask_is_byte = found;
}

// ---------------------------------------------------------------------------
// KcA: context fp32 -> fp16 main + e5m2 pack [aL, aH]
// ---------------------------------------------------------------------------
__global__ void k_convA(const float* __restrict__ src, int n4) {
    int i = blockIdx.x * blockDim.x + threadIdx.x;
    if (i >= n4) return;
    float4 v = ((const float4*)src)[i];
    __half h0 = __float2half_rn(v.x), h1 = __float2half_rn(v.y);
    __half h2 = __float2half_rn(v.z), h3 = __float2half_rn(v.w);
    float l0 = v.x - __half2float(h0);
    float l1 = v.y - __half2float(h1);
    float l2 = v.z - __half2float(h2);
    float l3 = v.w - __half2float(h3);
    __half2* hp = (__half2*)g_ctx16;
    hp[i * 2 + 0] = __halves2half2(h0, h1);
    hp[i * 2 + 1] = __halves2half2(h2, h3);
    // byte0 = e5m2(aL), byte1 = e5m2(aH)
    ushort4 pk;
    pk.x = pack_e5m2(v.x, l0);
    pk.y = pack_e5m2(v.y, l1);
    pk.z = pack_e5m2(v.z, l2);
    pk.w = pack_e5m2(v.w, l3);
    ((ushort4*)g_ctxp)[i] = pk;
}

// ---------------------------------------------------------------------------
// KcB: Wc fp32 -> fp16(512*w) + e5m2 pack [bH', bL']
// ---------------------------------------------------------------------------
__global__ void k_convB(const float* __restrict__ src, int n4) {
    int i = blockIdx.x * blockDim.x + threadIdx.x;
    if (i >= n4) return;
    float4 v = ((const float4*)src)[i];
    float x0 = v.x * BSCALE, x1 = v.y * BSCALE, x2 = v.z * BSCALE, x3 = v.w * BSCALE;
    __half h0 = __float2half_rn(x0), h1 = __float2half_rn(x1);
    __half h2 = __float2half_rn(x2), h3 = __float2half_rn(x3);
    float f0 = __half2float(h0), f1 = __half2float(h1);
    float f2 = __half2float(h2), f3 = __half2float(h3);
    __half2* hp = (__half2*)g_wc16;
    hp[i * 2 + 0] = __halves2half2(h0, h1);
    hp[i * 2 + 1] = __halves2half2(h2, h3);
    // byte0 = e5m2(bH'), byte1 = e5m2(bL')
    ushort4 pk;
    pk.x = pack_e5m2(x0 - f0, f0);
    pk.y = pack_e5m2(x1 - f1, f1);
    pk.z = pack_e5m2(x2 - f2, f2);
    pk.w = pack_e5m2(x3 - f3, f3);
    ((ushort4*)g_wcp)[i] = pk;
}

// ---------------------------------------------------------------------------
// K1: hb = inp@Wl.T + bl + bc ; zero g_cbar and g_att (warp-per-row, coalesced)
// ---------------------------------------------------------------------------
__global__ void __launch_bounds__(256) k1_hb(const float* __restrict__ inp,
                                             const float* __restrict__ Wl,
                                             const float* __restrict__ bl,
                                             const float* __restrict__ bc) {
    __shared__ float sin[IDIM];
    int b  = blockIdx.x >> 2;
    int hq = blockIdx.x & 3;
    int tid = threadIdx.x;
    int wid = tid >> 5, lane = tid & 31;

    sin[tid] = inp[b * IDIM + tid];
    sin[tid + 256] = inp[b * IDIM + tid + 256];
    g_att[b * SDIM + hq * 512 + tid * 2 + 0] = 0.0f;
    g_att[b * SDIM + hq * 512 + tid * 2 + 1] = 0.0f;
    if (tid < 128) g_cbar[b * IDIM + hq * 128 + tid] = 0.0f;
    __syncthreads();

    const float4* s4 = (const float4*)sin;
    #pragma unroll 1
    for (int r = wid; r < 128; r += 8) {
        int h = hq * 128 + r;
        const float4* w4 = (const float4*)(Wl + (size_t)h * IDIM);
        float acc = 0.0f;
        #pragma unroll
        for (int j = 0; j < 4; j++) {
            float4 w = w4[lane + 32 * j];
            float4 s = s4[lane + 32 * j];
            acc += w.x * s.x + w.y * s.y + w.z * s.z + w.w * s.w;
        }
        #pragma unroll
        for (int o = 16; o > 0; o >>= 1) acc += __shfl_xor_sync(0xffffffffu, acc, o);
        if (lane == 0) g_hb[b * HDIM + h] = acc + bl[h] + bc[h];
    }
}

// ---------------------------------------------------------------------------
// K2: fp16 main + e5m2 packed-correction GEMM + tanh + V reduction.
// acc accumulates 512*ctx; epilogue multiplies by 1/512.
// CTA tile 128(s) x 128(h); K=512 in 16 chunks of 32.
// Stage (32KB): A16 8K | AP 8K | B16 8K | BP 8K;  3 stages = 96KB -> 2 CTA/SM.
// All streams: 64-byte rows, shared swizzle + ldmatrix geometry.
// grid = B * 16(stile) * 4(htile) = 4096 CTAs, 256 threads.
// ---------------------------------------------------------------------------
#define ST_A16 0u
#define ST_AP  8192u
#define ST_B16 16384u
#define ST_BP  24576u
#define STAGE_BYTES 32768u
#define SMEM_K2 (3 * STAGE_BYTES)
#define NCHUNK 16

__global__ void __launch_bounds__(256, 2) k2_att_mma(const float* __restrict__ Vv) {
    extern __shared__ char smem[];
    __shared__ float sV[128], sHB[128], attred[128];
    uint32_t sb = smem_u32(smem);

    int tid  = threadIdx.x;
    int wid  = tid >> 5;
    int lane = tid & 31;
    int g    = lane >> 2;
    int tg   = lane & 3;
    int warp_m = wid & 1;
    int warp_n = wid >> 1;

    int bx = blockIdx.x;
    int b     = bx >> 6;
    int stile = (bx >> 2) & 15;
    int htile = bx & 3;
    int s0    = stile * 128;
    int hbase = htile * 128;
    int bb    = b * SDIM;

    if (tid < 128) {
        sV[tid]  = Vv[hbase + tid];
        sHB[tid] = g_hb[b * HDIM + hbase + tid];
        attred[tid] = 0.0f;
    }

    // chunk loader: 4 streams x (128 rows x 64B), all cp.async 16B.
    // idx -> r = idx>>2 (row), c = idx&3 (16B sector)
    auto loadAB = [&](int kc, uint32_t stage_base) {
        int k0 = kc * 32;
        #pragma unroll
        for (int j = 0; j < 2; j++) {
            int idx = j * 256 + tid;
            int r = idx >> 2, c = idx & 3;
            uint32_t off = ((uint32_t)(r * 64 + c * 16)) ^ SWZ8(r);
            const __half* sA16 = g_ctx16 + (size_t)(bb + s0 + r) * IDIM + k0 + c * 8;
            const unsigned short* sAP = g_ctxp + (size_t)(bb + s0 + r) * IDIM + k0 + c * 8;
            const __half* sB16 = g_wc16 + (size_t)(hbase + r) * IDIM + k0 + c * 8;
            const unsigned short* sBP = g_wcp + (size_t)(hbase + r) * IDIM + k0 + c * 8;
            CP16(stage_base + ST_A16 + off, sA16);
            CP16(stage_base + ST_AP  + off, sAP);
            CP16(stage_base + ST_B16 + off, sB16);
            CP16(stage_base + ST_BP  + off, sBP);
        }
        CP_COMMIT();
    };

    // shared fragment geometry (64B rows): identical for all 4 streams
    uint32_t axor = SWZ8(lane);   // depends on lane&7 = row&7 for both a and b
    uint32_t offA[4], offB[2];
    {
        int ar = lane & 15;
        uint32_t ak = (uint32_t)(lane & 16);
        #pragma unroll
        for (int t = 0; t < 4; t++)
            offA[t] = (uint32_t)((warp_m * 64 + t * 16 + ar) * 64) + ak;
        int brow = (lane & 7) + ((lane & 16) >> 1);
        uint32_t bk = (uint32_t)(((lane >> 3) & 1) * 16);
        #pragma unroll
        for (int p = 0; p < 2; p++)
            offB[p] = (uint32_t)((warp_n * 32 + p * 16 + brow) * 64) + bk;
    }

    float acc[4][4][4];
    #pragma unroll
    for (int t = 0; t < 4; t++)
        #pragma unroll
        for (int n = 0; n < 4; n++)
            #pragma unroll
            for (int c = 0; c < 4; c++) acc[t][n][c] = 0.0f;

    // ---- prologue
    loadAB(0, sb + 0u * STAGE_BYTES);
    loadAB(1, sb + 1u * STAGE_BYTES);

    #pragma unroll 1
    for (int i = 0; i < NCHUNK; i++) {
        if (i + 2 < NCHUNK)
            loadAB(i + 2, sb + (uint32_t)((i + 2) % 3) * STAGE_BYTES);
        if (i + 2 < NCHUNK)      { CP_WAIT(2); }
        else if (i + 1 < NCHUNK) { CP_WAIT(1); }
        else                     { CP_WAIT(0); }
        __syncthreads();

        uint32_t stb = sb + (uint32_t)(i % 3) * STAGE_BYTES;

        // fp16 main: 2 k16-steps (32B each)
        #pragma unroll
        for (int s = 0; s < 2; s++) {
            uint32_t so = (uint32_t)(s * 32);
            uint32_t afr[4][4], bfr[2][4];
            #pragma unroll
            for (int t = 0; t < 4; t++)
                LDSM4(afr[t], stb + ST_A16 + ((offA[t] + so) ^ axor));
            #pragma unroll
            for (int p = 0; p < 2; p++)
                LDSM4(bfr[p], stb + ST_B16 + ((offB[p] + so) ^ axor));
            #pragma unroll
            for (int t = 0; t < 4; t++)
                #pragma unroll
                for (int nt = 0; nt < 4; nt++) {
                    int p = nt >> 1;
                    int r0 = (nt & 1) * 2;
                    MMA_F16(acc[t][nt], afr[t], bfr[p][r0], bfr[p][r0 + 1]);
                }
        }
        // e5m2 correction: 2 k32-steps (32B each), same accumulator
        #pragma unroll
        for (int s = 0; s < 2; s++) {
            uint32_t so = (uint32_t)(s * 32);
            uint32_t afr[4][4], bfr[2][4];
            #pragma unroll
            for (int t = 0; t < 4; t++)
                LDSM4(afr[t], stb + ST_AP + ((offA[t] + so) ^ axor));
            #pragma unroll
            for (int p = 0; p < 2; p++)
                LDSM4(bfr[p], stb + ST_BP + ((offB[p] + so) ^ axor));
            #pragma unroll
            for (int t = 0; t < 4; t++)
                #pragma unroll
                for (int nt = 0; nt < 4; nt++) {
                    int p = nt >> 1;
                    int r0 = (nt & 1) * 2;
                    MMA_E5(acc[t][nt], afr[t], bfr[p][r0], bfr[p][r0 + 1]);
                }
        }
        __syncthreads();
    }

    // ---- epilogue: att[s] += sum_h V[h]*tanh(acc/512 + hb[h])
    float rowsum[8];
    #pragma unroll
    for (int r = 0; r < 8; r++) rowsum[r] = 0.0f;
    #pragma unroll
    for (int t = 0; t < 4; t++) {
        #pragma unroll
        for (int nt = 0; nt < 4; nt++) {
            int hh = warp_n * 32 + nt * 8 + tg * 2;
            float v0 = sV[hh], v1 = sV[hh + 1];
            float h0 = sHB[hh], h1 = sHB[hh + 1];
            float* c = acc[t][nt];
            rowsum[t * 2 + 0] += v0 * tanhf(c[0] * INV_BSCALE + h0)
                               + v1 * tanhf(c[1] * INV_BSCALE + h1);
            rowsum[t * 2 + 1] += v0 * tanhf(c[2] * INV_BSCALE + h0)
                               + v1 * tanhf(c[3] * INV_BSCALE + h1);
        }
    }
    #pragma unroll
    for (int r = 0; r < 8; r++) {
        float s = rowsum[r];
        s += __shfl_xor_sync(0xffffffffu, s, 1);
        s += __shfl_xor_sync(0xffffffffu, s, 2);
        if (tg == 0) {
            int row = warp_m * 64 + (r >> 1) * 16 + (r & 1) * 8 + g;
            atomicAdd(&attred[row], s);
        }
    }
    __syncthreads();
    if (tid < 128) atomicAdd(&g_att[b * SDIM + s0 + tid], attred[tid]);
}

// ---------------------------------------------------------------------------
// K3: masked softmax over S per batch -> alpha
// ---------------------------------------------------------------------------
__device__ __forceinline__ bool mask_at(const unsigned char* m, int idx, int is_byte) {
    if (is_byte) return m[idx] != 0;
    return ((const int*)m)[idx] != 0;
}

__global__ void k3_softmax(const unsigned char* __restrict__ mraw,
                           float* __restrict__ alpha) {
    __shared__ float red[256];
    int b = blockIdx.x;
    int tid = threadIdx.x;
    int is_byte = g_mask_is_byte;
    const float NEG_INF = __int_as_float(0xff800000);

    float lmax = NEG_INF;
    for (int s = tid; s < SDIM; s += 256)
        if (!mask_at(mraw, b * SDIM + s, is_byte))
            lmax = fmaxf(lmax, g_att[b * SDIM + s]);
    red[tid] = lmax;
    __syncthreads();
    for (int o = 128; o > 0; o >>= 1) {
        if (tid < o) red[tid] = fmaxf(red[tid], red[tid + o]);
        __syncthreads();
    }
    float smax = red[0];
    __syncthreads();

    float lsum = 0.0f;
    for (int s = tid; s < SDIM; s += 256) {
        float e = 0.0f;
        if (!mask_at(mraw, b * SDIM + s, is_byte))
            e = expf(g_att[b * SDIM + s] - smax);
        alpha[b * SDIM + s] = e;
        lsum += e;
    }
    red[tid] = lsum;
    __syncthreads();
    for (int o = 128; o > 0; o >>= 1) {
        if (tid < o) red[tid] += red[tid + o];
        __syncthreads();
    }
    float inv = 1.0f / red[0];
    __syncthreads();

    for (int s = tid; s < SDIM; s += 256)
        alpha[b * SDIM + s] *= inv;
}

// ---------------------------------------------------------------------------
// K4: cbar[b,i] = sum_s alpha[b,s] * context[b,s,i]
// ---------------------------------------------------------------------------
__global__ void k4_cbar(const float* __restrict__ context,
                        const float* __restrict__ alpha) {
    __shared__ float sal[128];
    int b  = blockIdx.y;
    int s0 = blockIdx.x * 128;
    int i  = threadIdx.x;
    if (i < 128) sal[i] = alpha[b * SDIM + s0 + i];
    __syncthreads();
    const float* cp = context + (size_t)b * SDIM * IDIM + (size_t)s0 * IDIM + i;
    float acc = 0.0f;
    #pragma unroll 4
    for (int s = 0; s < 128; s++) acc += sal[s] * cp[(size_t)s * IDIM];
    atomicAdd(&g_cbar[b * IDIM + i], acc);
}

// ---------------------------------------------------------------------------
// K5: hidden = Wc @ cbar + bc  (coalesced warp-per-row)
// ---------------------------------------------------------------------------
__global__ void __launch_bounds__(256) k5_out(const float* __restrict__ Wc,
                                              const float* __restrict__ bc,
                                              float* __restrict__ out) {
    __shared__ float sc[IDIM];
    int b  = blockIdx.x >> 2;
    int hq = blockIdx.x & 3;
    int tid = threadIdx.x;
    int wid = tid >> 5, lane = tid & 31;

    sc[tid] = g_cbar[b * IDIM + tid];
    sc[tid + 256] = g_cbar[b * IDIM + tid + 256];
    __syncthreads();

    const float4* s4 = (const float4*)sc;
    #pragma unroll 1
    for (int r = wid; r < 128; r += 8) {
        int h = hq * 128 + r;
        const float4* w4 = (const float4*)(Wc + (size_t)h * IDIM);
        float acc = 0.0f;
        #pragma unroll
        for (int j = 0; j < 4; j++) {
            float4 w = w4[lane + 32 * j];
            float4 s = s4[lane + 32 * j];
            acc += w.x * s.x + w.y * s.y + w.z * s.z + w.w * s.w;
        }
        #pragma unroll
        for (int o = 16; o > 0; o >>= 1) acc += __shfl_xor_sync(0xffffffffu, acc, o);
        if (lane == 0) out[b * HDIM + h] = acc + bc[h];
    }
}

// ---------------------------------------------------------------------------
extern "C" void kernel_launch(void* const* d_in, const int* in_sizes, int n_in,
                              void* d_out, int out_size) {
    const float* inp          = (const float*)d_in[0];
    const float* context      = (const float*)d_in[1];
    const unsigned char* mraw = (const unsigned char*)d_in[2];
    const float* Wl           = (const float*)d_in[3];
    const float* bl           = (const float*)d_in[4];
    const float* Wc           = (const float*)d_in[5];
    const float* bc           = (const float*)d_in[6];
    const float* Vv           = (const float*)d_in[7];

    float* out    = (float*)d_out;
    float* hidden = out;                   // [B, HID]
    float* alpha  = out + BDIM * HDIM;     // [B, S]

    cudaFuncSetAttribute(k2_att_mma, cudaFuncAttributeMaxDynamicSharedMemorySize, SMEM_K2);

    k0_detect<<<1, 256>>>(mraw);
    int n4c = BDIM * SDIM * IDIM / 4;
    k_convA<<<n4c / 256, 256>>>(context, n4c);
    int n4w = HDIM * IDIM / 4;
    k_convB<<<n4w / 256, 256>>>(Wc, n4w);
    k1_hb<<<BDIM * 4, 256>>>(inp, Wl, bl, bc);
    k2_att_mma<<<BDIM * 16 * 4, 256, SMEM_K2>>>(Vv);
    k3_softmax<<<BDIM, 256>>>(mraw, alpha);
    k4_cbar<<<dim3(SDIM / 128, BDIM), 512>>>(context, alpha);
    k5_out<<<BDIM * 4, 256>>>(Wc, bc, hidden);
}

// round 14
// speedup vs baseline: 2.0460x; 2.0460x over previous
#include <cuda_runtime.h>
#include <cuda_fp16.h>
#include <math.h>
#include <stdint.h>

#define BDIM 64
#define SDIM 2048
#define IDIM 512
#define HDIM 512
#define BSCALE 512.0f
#define INV_BSCALE (1.0f / 512.0f)

// ---------------- device scratch (no cudaMalloc allowed) -------------------
__device__ float g_hb[BDIM * HDIM];
__device__ float g_att[BDIM * SDIM];
__device__ float g_cbar[BDIM * IDIM];
__device__ int   g_mask_is_byte;

__device__ __half g_ctx16[BDIM * SDIM * IDIM];   // fp16(ctx)
__device__ __half g_wc16 [HDIM * IDIM];          // fp16(512*Wc)

// ---------------- PTX helpers (sm_80-level only) ----------------------------
__device__ __forceinline__ uint32_t smem_u32(const void* p) {
    uint32_t a;
    asm("{ .reg .u64 t; cvta.to.shared.u64 t, %1; cvt.u32.u64 %0, t; }" : "=r"(a) : "l"(p));
    return a;
}
#define CP16(dst, src) asm volatile("cp.async.cg.shared.global [%0], [%1], 16;" :: "r"(dst), "l"(src))
#define CP_COMMIT()    asm volatile("cp.async.commit_group;" ::: "memory")
#define CP_WAIT(n)     asm volatile("cp.async.wait_group %0;" :: "n"(n) : "memory")

#define LDSM4(r, a)                                                           \
    asm volatile("ldmatrix.sync.aligned.m8n8.x4.shared.b16 {%0,%1,%2,%3}, [%4];" \
        : "=r"((r)[0]), "=r"((r)[1]), "=r"((r)[2]), "=r"((r)[3]) : "r"(a))

#define MMA_F16(c, a, b0, b1)                                                 \
    asm volatile("mma.sync.aligned.m16n8k16.row.col.f32.f16.f16.f32 "         \
        "{%0,%1,%2,%3},{%4,%5,%6,%7},{%8,%9},{%0,%1,%2,%3};"                  \
        : "+f"((c)[0]), "+f"((c)[1]), "+f"((c)[2]), "+f"((c)[3])              \
        : "r"((a)[0]), "r"((a)[1]), "r"((a)[2]), "r"((a)[3]), "r"(b0), "r"(b1))

#define SWZ8(r) ((uint32_t)((((r) & 3) ^ (((r) >> 2) & 1)) << 4))

// ---------------------------------------------------------------------------
// K0: detect mask storage (int32 vs uint8)
// ---------------------------------------------------------------------------
__global__ void k0_detect(const unsigned char* __restrict__ mraw) {
    __shared__ int found;
    if (threadIdx.x == 0) found = 0;
    __syncthreads();
    int acc = 0;
    for (int i = threadIdx.x; i < 4096; i += 256)
        if ((i & 3) != 0 && mraw[i] != 0) acc = 1;
    if (acc) atomicOr(&found, 1);
    __syncthreads();
    if (threadIdx.x == 0) g_mask_is_byte = found;
}

// ---------------------------------------------------------------------------
// KcA: context fp32 -> fp16
// ---------------------------------------------------------------------------
__global__ void k_convA(const float* __restrict__ src, int n4) {
    int i = blockIdx.x * blockDim.x + threadIdx.x;
    if (i >= n4) return;
    float4 v = ((const float4*)src)[i];
    __half2* hp = (__half2*)g_ctx16;
    hp[i * 2 + 0] = __halves2half2(__float2half_rn(v.x), __float2half_rn(v.y));
    hp[i * 2 + 1] = __halves2half2(__float2half_rn(v.z), __float2half_rn(v.w));
}

// ---------------------------------------------------------------------------
// KcB: Wc fp32 -> fp16(512*w)
// ---------------------------------------------------------------------------
__global__ void k_convB(const float* __restrict__ src, int n4) {
    int i = blockIdx.x * blockDim.x + threadIdx.x;
    if (i >= n4) return;
    float4 v = ((const float4*)src)[i];
    __half2* hp = (__half2*)g_wc16;
    hp[i * 2 + 0] = __halves2half2(__float2half_rn(v.x * BSCALE), __float2half_rn(v.y * BSCALE));
    hp[i * 2 + 1] = __halves2half2(__float2half_rn(v.z * BSCALE), __float2half_rn(v.w * BSCALE));
}

// ---------------------------------------------------------------------------
// K1: hb = inp@Wl.T + bl + bc ; zero g_cbar and g_att (warp-per-row, coalesced)
// ---------------------------------------------------------------------------
__global__ void __launch_bounds__(256) k1_hb(const float* __restrict__ inp,
                                             const float* __restrict__ Wl,
                                             const float* __restrict__ bl,
                                             const float* __restrict__ bc) {
    __shared__ float sin[IDIM];
    int b  = blockIdx.x >> 2;
    int hq = blockIdx.x & 3;
    int tid = threadIdx.x;
    int wid = tid >> 5, lane = tid & 31;

    sin[tid] = inp[b * IDIM + tid];
    sin[tid + 256] = inp[b * IDIM + tid + 256];
    g_att[b * SDIM + hq * 512 + tid * 2 + 0] = 0.0f;
    g_att[b * SDIM + hq * 512 + tid * 2 + 1] = 0.0f;
    if (tid < 128) g_cbar[b * IDIM + hq * 128 + tid] = 0.0f;
    __syncthreads();

    const float4* s4 = (const float4*)sin;
    #pragma unroll 1
    for (int r = wid; r < 128; r += 8) {
        int h = hq * 128 + r;
        const float4* w4 = (const float4*)(Wl + (size_t)h * IDIM);
        float acc = 0.0f;
        #pragma unroll
        for (int j = 0; j < 4; j++) {
            float4 w = w4[lane + 32 * j];
            float4 s = s4[lane + 32 * j];
            acc += w.x * s.x + w.y * s.y + w.z * s.z + w.w * s.w;
        }
        #pragma unroll
        for (int o = 16; o > 0; o >>= 1) acc += __shfl_xor_sync(0xffffffffu, acc, o);
        if (lane == 0) g_hb[b * HDIM + h] = acc + bl[h] + bc[h];
    }
}

// ---------------------------------------------------------------------------
// K2: single-term fp16 GEMM + tanh + V reduction.
// A = fp16(ctx), B = fp16(512*Wc), both preconverted, pure cp.async.
// CTA tile 128(s) x 128(h); K=512 in 16 chunks of 32.
// Stage (16KB): A16 8K | B16 8K;  4 stages = 64KB -> 2 CTA/SM.
// 64-byte rows, SWZ8 swizzle (validated R13).
// grid = B * 16(stile) * 4(htile) = 4096 CTAs, 256 threads.
// ---------------------------------------------------------------------------
#define ST_A16 0u
#define ST_B16 8192u
#define STAGE_BYTES 16384u
#define NSTAGE 4
#define SMEM_K2 (NSTAGE * STAGE_BYTES)
#define NCHUNK 16

__global__ void __launch_bounds__(256, 2) k2_att_mma(const float* __restrict__ Vv) {
    extern __shared__ char smem[];
    __shared__ float sV[128], sHB[128], attred[128];
    uint32_t sb = smem_u32(smem);

    int tid  = threadIdx.x;
    int wid  = tid >> 5;
    int lane = tid & 31;
    int g    = lane >> 2;
    int tg   = lane & 3;
    int warp_m = wid & 1;
    int warp_n = wid >> 1;

    int bx = blockIdx.x;
    int b     = bx >> 6;
    int stile = (bx >> 2) & 15;
    int htile = bx & 3;
    int s0    = stile * 128;
    int hbase = htile * 128;
    int bb    = b * SDIM;

    if (tid < 128) {
        sV[tid]  = Vv[hbase + tid];
        sHB[tid] = g_hb[b * HDIM + hbase + tid];
        attred[tid] = 0.0f;
    }

    // chunk loader: 2 streams x (128 rows x 64B), cp.async 16B.
    auto loadAB = [&](int kc, uint32_t stage_base) {
        int k0 = kc * 32;
        #pragma unroll
        for (int j = 0; j < 2; j++) {
            int idx = j * 256 + tid;
            int r = idx >> 2, c = idx & 3;
            uint32_t off = ((uint32_t)(r * 64 + c * 16)) ^ SWZ8(r);
            const __half* sA16 = g_ctx16 + (size_t)(bb + s0 + r) * IDIM + k0 + c * 8;
            const __half* sB16 = g_wc16 + (size_t)(hbase + r) * IDIM + k0 + c * 8;
            CP16(stage_base + ST_A16 + off, sA16);
            CP16(stage_base + ST_B16 + off, sB16);
        }
        CP_COMMIT();
    };

    // fragment geometry (64B rows)
    uint32_t axor = SWZ8(lane);
    uint32_t offA[4], offB[2];
    {
        int ar = lane & 15;
        uint32_t ak = (uint32_t)(lane & 16);
        #pragma unroll
        for (int t = 0; t < 4; t++)
            offA[t] = (uint32_t)((warp_m * 64 + t * 16 + ar) * 64) + ak;
        int brow = (lane & 7) + ((lane & 16) >> 1);
        uint32_t bk = (uint32_t)(((lane >> 3) & 1) * 16);
        #pragma unroll
        for (int p = 0; p < 2; p++)
            offB[p] = (uint32_t)((warp_n * 32 + p * 16 + brow) * 64) + bk;
    }

    float acc[4][4][4];
    #pragma unroll
    for (int t = 0; t < 4; t++)
        #pragma unroll
        for (int n = 0; n < 4; n++)
            #pragma unroll
            for (int c = 0; c < 4; c++) acc[t][n][c] = 0.0f;

    // ---- prologue: fill 3 of 4 stages
    loadAB(0, sb + 0u * STAGE_BYTES);
    loadAB(1, sb + 1u * STAGE_BYTES);
    loadAB(2, sb + 2u * STAGE_BYTES);

    #pragma unroll 1
    for (int i = 0; i < NCHUNK; i++) {
        if (i + 3 < NCHUNK)
            loadAB(i + 3, sb + (uint32_t)((i + 3) % NSTAGE) * STAGE_BYTES);
        if (i + 3 < NCHUNK)      { CP_WAIT(3); }
        else if (i + 2 < NCHUNK) { CP_WAIT(2); }
        else if (i + 1 < NCHUNK) { CP_WAIT(1); }
        else                     { CP_WAIT(0); }
        __syncthreads();

        uint32_t stb = sb + (uint32_t)(i % NSTAGE) * STAGE_BYTES;

        #pragma unroll
        for (int s = 0; s < 2; s++) {            // 2 k16 steps per chunk32
            uint32_t so = (uint32_t)(s * 32);
            uint32_t afr[4][4], bfr[2][4];
            #pragma unroll
            for (int t = 0; t < 4; t++)
                LDSM4(afr[t], stb + ST_A16 + ((offA[t] + so) ^ axor));
            #pragma unroll
            for (int p = 0; p < 2; p++)
                LDSM4(bfr[p], stb + ST_B16 + ((offB[p] + so) ^ axor));
            #pragma unroll
            for (int t = 0; t < 4; t++)
                #pragma unroll
                for (int nt = 0; nt < 4; nt++) {
                    int p = nt >> 1;
                    int r0 = (nt & 1) * 2;
                    MMA_F16(acc[t][nt], afr[t], bfr[p][r0], bfr[p][r0 + 1]);
                }
        }
        __syncthreads();
    }

    // ---- epilogue: att[s] += sum_h V[h]*tanh(acc/512 + hb[h])
    float rowsum[8];
    #pragma unroll
    for (int r = 0; r < 8; r++) rowsum[r] = 0.0f;
    #pragma unroll
    for (int t = 0; t < 4; t++) {
        #pragma unroll
        for (int nt = 0; nt < 4; nt++) {
            int hh = warp_n * 32 + nt * 8 + tg * 2;
            float v0 = sV[hh], v1 = sV[hh + 1];
            float h0 = sHB[hh], h1 = sHB[hh + 1];
            float* c = acc[t][nt];
            rowsum[t * 2 + 0] += v0 * tanhf(c[0] * INV_BSCALE + h0)
                               + v1 * tanhf(c[1] * INV_BSCALE + h1);
            rowsum[t * 2 + 1] += v0 * tanhf(c[2] * INV_BSCALE + h0)
                               + v1 * tanhf(c[3] * INV_BSCALE + h1);
        }
    }
    #pragma unroll
    for (int r = 0; r < 8; r++) {
        float s = rowsum[r];
        s += __shfl_xor_sync(0xffffffffu, s, 1);
        s += __shfl_xor_sync(0xffffffffu, s, 2);
        if (tg == 0) {
            int row = warp_m * 64 + (r >> 1) * 16 + (r & 1) * 8 + g;
            atomicAdd(&attred[row], s);
        }
    }
    __syncthreads();
    if (tid < 128) atomicAdd(&g_att[b * SDIM + s0 + tid], attred[tid]);
}

// ---------------------------------------------------------------------------
// K3: masked softmax over S per batch -> alpha
// ---------------------------------------------------------------------------
__device__ __forceinline__ bool mask_at(const unsigned char* m, int idx, int is_byte) {
    if (is_byte) return m[idx] != 0;
    return ((const int*)m)[idx] != 0;
}

__global__ void k3_softmax(const unsigned char* __restrict__ mraw,
                           float* __restrict__ alpha) {
    __shared__ float red[256];
    int b = blockIdx.x;
    int tid = threadIdx.x;
    int is_byte = g_mask_is_byte;
    const float NEG_INF = __int_as_float(0xff800000);

    float lmax = NEG_INF;
    for (int s = tid; s < SDIM; s += 256)
        if (!mask_at(mraw, b * SDIM + s, is_byte))
            lmax = fmaxf(lmax, g_att[b * SDIM + s]);
    red[tid] = lmax;
    __syncthreads();
    for (int o = 128; o > 0; o >>= 1) {
        if (tid < o) red[tid] = fmaxf(red[tid], red[tid + o]);
        __syncthreads();
    }
    float smax = red[0];
    __syncthreads();

    float lsum = 0.0f;
    for (int s = tid; s < SDIM; s += 256) {
        float e = 0.0f;
        if (!mask_at(mraw, b * SDIM + s, is_byte))
            e = expf(g_att[b * SDIM + s] - smax);
        alpha[b * SDIM + s] = e;
        lsum += e;
    }
    red[tid] = lsum;
    __syncthreads();
    for (int o = 128; o > 0; o >>= 1) {
        if (tid < o) red[tid] += red[tid + o];
        __syncthreads();
    }
    float inv = 1.0f / red[0];
    __syncthreads();

    for (int s = tid; s < SDIM; s += 256)
        alpha[b * SDIM + s] *= inv;
}

// ---------------------------------------------------------------------------
// K4: cbar[b,i] = sum_s alpha[b,s] * context[b,s,i]
// ---------------------------------------------------------------------------
__global__ void k4_cbar(const float* __restrict__ context,
                        const float* __restrict__ alpha) {
    __shared__ float sal[128];
    int b  = blockIdx.y;
    int s0 = blockIdx.x * 128;
    int i  = threadIdx.x;
    if (i < 128) sal[i] = alpha[b * SDIM + s0 + i];
    __syncthreads();
    const float* cp = context + (size_t)b * SDIM * IDIM + (size_t)s0 * IDIM + i;
    float acc = 0.0f;
    #pragma unroll 4
    for (int s = 0; s < 128; s++) acc += sal[s] * cp[(size_t)s * IDIM];
    atomicAdd(&g_cbar[b * IDIM + i], acc);
}

// ---------------------------------------------------------------------------
// K5: hidden = Wc @ cbar + bc  (coalesced warp-per-row)
// ---------------------------------------------------------------------------
__global__ void __launch_bounds__(256) k5_out(const float* __restrict__ Wc,
                                              const float* __restrict__ bc,
                                              float* __restrict__ out) {
    __shared__ float sc[IDIM];
    int b  = blockIdx.x >> 2;
    int hq = blockIdx.x & 3;
    int tid = threadIdx.x;
    int wid = tid >> 5, lane = tid & 31;

    sc[tid] = g_cbar[b * IDIM + tid];
    sc[tid + 256] = g_cbar[b * IDIM + tid + 256];
    __syncthreads();

    const float4* s4 = (const float4*)sc;
    #pragma unroll 1
    for (int r = wid; r < 128; r += 8) {
        int h = hq * 128 + r;
        const float4* w4 = (const float4*)(Wc + (size_t)h * IDIM);
        float acc = 0.0f;
        #pragma unroll
        for (int j = 0; j < 4; j++) {
            float4 w = w4[lane + 32 * j];
            float4 s = s4[lane + 32 * j];
            acc += w.x * s.x + w.y * s.y + w.z * s.z + w.w * s.w;
        }
        #pragma unroll
        for (int o = 16; o > 0; o >>= 1) acc += __shfl_xor_sync(0xffffffffu, acc, o);
        if (lane == 0) out[b * HDIM + h] = acc + bc[h];
    }
}

// ---------------------------------------------------------------------------
extern "C" void kernel_launch(void* const* d_in, const int* in_sizes, int n_in,
                              void* d_out, int out_size) {
    const float* inp          = (const float*)d_in[0];
    const float* context      = (const float*)d_in[1];
    const unsigned char* mraw = (const unsigned char*)d_in[2];
    const float* Wl           = (const float*)d_in[3];
    const float* bl           = (const float*)d_in[4];
    const float* Wc           = (const float*)d_in[5];
    const float* bc           = (const float*)d_in[6];
    const float* Vv           = (const float*)d_in[7];

    float* out    = (float*)d_out;
    float* hidden = out;                   // [B, HID]
    float* alpha  = out + BDIM * HDIM;     // [B, S]

    cudaFuncSetAttribute(k2_att_mma, cudaFuncAttributeMaxDynamicSharedMemorySize, SMEM_K2);

    k0_detect<<<1, 256>>>(mraw);
    int n4c = BDIM * SDIM * IDIM / 4;
    k_convA<<<n4c / 256, 256>>>(context, n4c);
    int n4w = HDIM * IDIM / 4;
    k_convB<<<n4w / 256, 256>>>(Wc, n4w);
    k1_hb<<<BDIM * 4, 256>>>(inp, Wl, bl, bc);
    k2_att_mma<<<BDIM * 16 * 4, 256, SMEM_K2>>>(Vv);
    k3_softmax<<<BDIM, 256>>>(mraw, alpha);
    k4_cbar<<<dim3(SDIM / 128, BDIM), 512>>>(context, alpha);
    k5_out<<<BDIM * 4, 256>>>(Wc, bc, hidden);
}

// round 15
// speedup vs baseline: 2.2556x; 1.1024x over previous
#include <cuda_runtime.h>
#include <cuda_fp16.h>
#include <math.h>
#include <stdint.h>

#define BDIM 64
#define SDIM 2048
#define IDIM 512
#define HDIM 512
#define BSCALE 512.0f
#define INV_BSCALE (1.0f / 512.0f)

// ---------------- device scratch (no cudaMalloc allowed) -------------------
__device__ float g_hb[BDIM * HDIM];
__device__ float g_att[BDIM * SDIM];
__device__ float g_cbar[BDIM * IDIM];
__device__ int   g_mask_is_byte;

__device__ __half g_ctx16[BDIM * SDIM * IDIM];   // fp16(ctx)
__device__ __half g_wc16 [HDIM * IDIM];          // fp16(512*Wc)

// ---------------- PTX helpers (sm_80-level only) ----------------------------
__device__ __forceinline__ uint32_t smem_u32(const void* p) {
    uint32_t a;
    asm("{ .reg .u64 t; cvta.to.shared.u64 t, %1; cvt.u32.u64 %0, t; }" : "=r"(a) : "l"(p));
    return a;
}
#define CP16(dst, src) asm volatile("cp.async.cg.shared.global [%0], [%1], 16;" :: "r"(dst), "l"(src))
#define CP_COMMIT()    asm volatile("cp.async.commit_group;" ::: "memory")
#define CP_WAIT(n)     asm volatile("cp.async.wait_group %0;" :: "n"(n) : "memory")

#define LDSM4(r, a)                                                           \
    asm volatile("ldmatrix.sync.aligned.m8n8.x4.shared.b16 {%0,%1,%2,%3}, [%4];" \
        : "=r"((r)[0]), "=r"((r)[1]), "=r"((r)[2]), "=r"((r)[3]) : "r"(a))

#define MMA_F16(c, a, b0, b1)                                                 \
    asm volatile("mma.sync.aligned.m16n8k16.row.col.f32.f16.f16.f32 "         \
        "{%0,%1,%2,%3},{%4,%5,%6,%7},{%8,%9},{%0,%1,%2,%3};"                  \
        : "+f"((c)[0]), "+f"((c)[1]), "+f"((c)[2]), "+f"((c)[3])              \
        : "r"((a)[0]), "r"((a)[1]), "r"((a)[2]), "r"((a)[3]), "r"(b0), "r"(b1))

// fast tanh: clamped exp form; abs err ~1e-6 (tanh(10)=1-8e-9)
__device__ __forceinline__ float fast_tanh(float x) {
    float xc = fminf(fmaxf(x, -10.0f), 10.0f);
    float e  = __expf(2.0f * xc);
    return __fdividef(e - 1.0f, e + 1.0f);
}

// ---------------------------------------------------------------------------
// K0: detect mask storage (int32 vs uint8)
// ---------------------------------------------------------------------------
__global__ void k0_detect(const unsigned char* __restrict__ mraw) {
    __shared__ int found;
    if (threadIdx.x == 0) found = 0;
    __syncthreads();
    int acc = 0;
    for (int i = threadIdx.x; i < 4096; i += 256)
        if ((i & 3) != 0 && mraw[i] != 0) acc = 1;
    if (acc) atomicOr(&found, 1);
    __syncthreads();
    if (threadIdx.x == 0) g_mask_is_byte = found;
}

// ---------------------------------------------------------------------------
// KcA: context fp32 -> fp16
// ---------------------------------------------------------------------------
__global__ void k_convA(const float* __restrict__ src, int n4) {
    int i = blockIdx.x * blockDim.x + threadIdx.x;
    if (i >= n4) return;
    float4 v = ((const float4*)src)[i];
    __half2* hp = (__half2*)g_ctx16;
    hp[i * 2 + 0] = __halves2half2(__float2half_rn(v.x), __float2half_rn(v.y));
    hp[i * 2 + 1] = __halves2half2(__float2half_rn(v.z), __float2half_rn(v.w));
}

// ---------------------------------------------------------------------------
// KcB: Wc fp32 -> fp16(512*w)
// ---------------------------------------------------------------------------
__global__ void k_convB(const float* __restrict__ src, int n4) {
    int i = blockIdx.x * blockDim.x + threadIdx.x;
    if (i >= n4) return;
    float4 v = ((const float4*)src)[i];
    __half2* hp = (__half2*)g_wc16;
    hp[i * 2 + 0] = __halves2half2(__float2half_rn(v.x * BSCALE), __float2half_rn(v.y * BSCALE));
    hp[i * 2 + 1] = __halves2half2(__float2half_rn(v.z * BSCALE), __float2half_rn(v.w * BSCALE));
}

// ---------------------------------------------------------------------------
// K1: hb = inp@Wl.T + bl + bc ; zero g_cbar and g_att.
// grid(B*8) -- block handles 64 h rows; warp-per-row, coalesced float4 reads.
// ---------------------------------------------------------------------------
__global__ void __launch_bounds__(256) k1_hb(const float* __restrict__ inp,
                                             const float* __restrict__ Wl,
                                             const float* __restrict__ bl,
                                             const float* __restrict__ bc) {
    __shared__ float sin[IDIM];
    int b  = blockIdx.x >> 3;
    int ho = (blockIdx.x & 7) * 64;
    int tid = threadIdx.x;
    int wid = tid >> 5, lane = tid & 31;

    sin[tid] = inp[b * IDIM + tid];
    sin[tid + 256] = inp[b * IDIM + tid + 256];
    g_att[b * SDIM + (blockIdx.x & 7) * 256 + tid] = 0.0f;
    if (tid < 64) g_cbar[b * IDIM + ho + tid] = 0.0f;
    __syncthreads();

    const float4* s4 = (const float4*)sin;
    #pragma unroll 1
    for (int r = wid; r < 64; r += 8) {
        int h = ho + r;
        const float4* w4 = (const float4*)(Wl + (size_t)h * IDIM);
        float acc = 0.0f;
        #pragma unroll
        for (int j = 0; j < 4; j++) {
            float4 w = w4[lane + 32 * j];
            float4 s = s4[lane + 32 * j];
            acc += w.x * s.x + w.y * s.y + w.z * s.z + w.w * s.w;
        }
        #pragma unroll
        for (int o = 16; o > 0; o >>= 1) acc += __shfl_xor_sync(0xffffffffu, acc, o);
        if (lane == 0) g_hb[b * HDIM + h] = acc + bl[h] + bc[h];
    }
}

// ---------------------------------------------------------------------------
// K2: single-term fp16 GEMM + fast-tanh + V reduction.
// A = fp16(ctx), B = fp16(512*Wc), pure cp.async.
// CTA tile 128(s) x 128(h); K=512 in 8 chunks of 64 (128B rows, R7 geometry).
// Stage (32KB): A16 16K | B16 16K;  3 stages = 96KB -> 2 CTA/SM.
// grid = B * 16(stile) * 4(htile) = 4096 CTAs, 256 threads.
// ---------------------------------------------------------------------------
#define ST_A16 0u
#define ST_B16 16384u
#define STAGE_BYTES 32768u
#define NSTAGE 3
#define SMEM_K2 (NSTAGE * STAGE_BYTES)
#define NCHUNK 8

__global__ void __launch_bounds__(256, 2) k2_att_mma(const float* __restrict__ Vv) {
    extern __shared__ char smem[];
    __shared__ float sV[128], sHB[128], attred[128];
    uint32_t sb = smem_u32(smem);

    int tid  = threadIdx.x;
    int wid  = tid >> 5;
    int lane = tid & 31;
    int g    = lane >> 2;
    int tg   = lane & 3;
    int warp_m = wid & 1;
    int warp_n = wid >> 1;

    int bx = blockIdx.x;
    int b     = bx >> 6;
    int stile = (bx >> 2) & 15;
    int htile = bx & 3;
    int s0    = stile * 128;
    int hbase = htile * 128;
    int bb    = b * SDIM;

    if (tid < 128) {
        sV[tid]  = Vv[hbase + tid];
        sHB[tid] = g_hb[b * HDIM + hbase + tid];
        attred[tid] = 0.0f;
    }

    // chunk loader: 2 streams x (128 rows x 128B), cp.async 16B, (r&7)<<4 swizzle
    auto loadAB = [&](int kc, uint32_t stage_base) {
        int k0 = kc * 64;
        #pragma unroll
        for (int j = 0; j < 4; j++) {
            int idx = j * 256 + tid;
            int r = idx >> 3, c = idx & 7;
            uint32_t off = ((uint32_t)(r * 128 + c * 16)) ^ ((uint32_t)(r & 7) << 4);
            const __half* sA16 = g_ctx16 + (size_t)(bb + s0 + r) * IDIM + k0 + c * 8;
            const __half* sB16 = g_wc16 + (size_t)(hbase + r) * IDIM + k0 + c * 8;
            CP16(stage_base + ST_A16 + off, sA16);
            CP16(stage_base + ST_B16 + off, sB16);
        }
        CP_COMMIT();
    };

    // fragment geometry (128B rows, R7-validated)
    int arow  = warp_m * 64 + (lane & 15);
    uint32_t akoff = (uint32_t)(lane & 16);
    uint32_t axor  = (uint32_t)((lane & 7) << 4);
    int brow  = (lane & 7) + ((lane & 16) >> 1);
    uint32_t bkoff = (uint32_t)(((lane >> 3) & 1) * 16);

    uint32_t offA[4], offB[2];
    #pragma unroll
    for (int t = 0; t < 4; t++) offA[t] = (uint32_t)((arow + t * 16) * 128) + akoff;
    #pragma unroll
    for (int p = 0; p < 2; p++) offB[p] = (uint32_t)((warp_n * 32 + p * 16 + brow) * 128) + bkoff;

    float acc[4][4][4];
    #pragma unroll
    for (int t = 0; t < 4; t++)
        #pragma unroll
        for (int n = 0; n < 4; n++)
            #pragma unroll
            for (int c = 0; c < 4; c++) acc[t][n][c] = 0.0f;

    // ---- prologue: fill 2 of 3 stages
    loadAB(0, sb + 0u * STAGE_BYTES);
    loadAB(1, sb + 1u * STAGE_BYTES);

    #pragma unroll 1
    for (int i = 0; i < NCHUNK; i++) {
        if (i + 2 < NCHUNK)
            loadAB(i + 2, sb + (uint32_t)((i + 2) % NSTAGE) * STAGE_BYTES);
        if (i + 2 < NCHUNK)      { CP_WAIT(2); }
        else if (i + 1 < NCHUNK) { CP_WAIT(1); }
        else                     { CP_WAIT(0); }
        __syncthreads();

        uint32_t stb = sb + (uint32_t)(i % NSTAGE) * STAGE_BYTES;

        #pragma unroll
        for (int q = 0; q < 4; q++) {            // 4 k16 steps per chunk64
            uint32_t qb = (uint32_t)(q * 32);
            uint32_t afr[4][4], bfr[2][4];
            #pragma unroll
            for (int t = 0; t < 4; t++)
                LDSM4(afr[t], stb + ST_A16 + ((offA[t] + qb) ^ axor));
            #pragma unroll
            for (int p = 0; p < 2; p++)
                LDSM4(bfr[p], stb + ST_B16 + ((offB[p] + qb) ^ axor));
            #pragma unroll
            for (int t = 0; t < 4; t++)
                #pragma unroll
                for (int nt = 0; nt < 4; nt++) {
                    int p = nt >> 1;
                    int r0 = (nt & 1) * 2;
                    MMA_F16(acc[t][nt], afr[t], bfr[p][r0], bfr[p][r0 + 1]);
                }
        }
        __syncthreads();
    }

    // ---- epilogue: att[s] += sum_h V[h]*fast_tanh(acc/512 + hb[h])
    float rowsum[8];
    #pragma unroll
    for (int r = 0; r < 8; r++) rowsum[r] = 0.0f;
    #pragma unroll
    for (int t = 0; t < 4; t++) {
        #pragma unroll
        for (int nt = 0; nt < 4; nt++) {
            int hh = warp_n * 32 + nt * 8 + tg * 2;
            float v0 = sV[hh], v1 = sV[hh + 1];
            float h0 = sHB[hh], h1 = sHB[hh + 1];
            float* c = acc[t][nt];
            rowsum[t * 2 + 0] += v0 * fast_tanh(c[0] * INV_BSCALE + h0)
                               + v1 * fast_tanh(c[1] * INV_BSCALE + h1);
            rowsum[t * 2 + 1] += v0 * fast_tanh(c[2] * INV_BSCALE + h0)
                               + v1 * fast_tanh(c[3] * INV_BSCALE + h1);
        }
    }
    #pragma unroll
    for (int r = 0; r < 8; r++) {
        float s = rowsum[r];
        s += __shfl_xor_sync(0xffffffffu, s, 1);
        s += __shfl_xor_sync(0xffffffffu, s, 2);
        if (tg == 0) {
            int row = warp_m * 64 + (r >> 1) * 16 + (r & 1) * 8 + g;
            atomicAdd(&attred[row], s);
        }
    }
    __syncthreads();
    if (tid < 128) atomicAdd(&g_att[b * SDIM + s0 + tid], attred[tid]);
}

// ---------------------------------------------------------------------------
// K3: masked softmax over S per batch -> alpha
// ---------------------------------------------------------------------------
__device__ __forceinline__ bool mask_at(const unsigned char* m, int idx, int is_byte) {
    if (is_byte) return m[idx] != 0;
    return ((const int*)m)[idx] != 0;
}

__global__ void k3_softmax(const unsigned char* __restrict__ mraw,
                           float* __restrict__ alpha) {
    __shared__ float red[256];
    int b = blockIdx.x;
    int tid = threadIdx.x;
    int is_byte = g_mask_is_byte;
    const float NEG_INF = __int_as_float(0xff800000);

    float lmax = NEG_INF;
    for (int s = tid; s < SDIM; s += 256)
        if (!mask_at(mraw, b * SDIM + s, is_byte))
            lmax = fmaxf(lmax, g_att[b * SDIM + s]);
    red[tid] = lmax;
    __syncthreads();
    for (int o = 128; o > 0; o >>= 1) {
        if (tid < o) red[tid] = fmaxf(red[tid], red[tid + o]);
        __syncthreads();
    }
    float smax = red[0];
    __syncthreads();

    float lsum = 0.0f;
    for (int s = tid; s < SDIM; s += 256) {
        float e = 0.0f;
        if (!mask_at(mraw, b * SDIM + s, is_byte))
            e = expf(g_att[b * SDIM + s] - smax);
        alpha[b * SDIM + s] = e;
        lsum += e;
    }
    red[tid] = lsum;
    __syncthreads();
    for (int o = 128; o > 0; o >>= 1) {
        if (tid < o) red[tid] += red[tid + o];
        __syncthreads();
    }
    float inv = 1.0f / red[0];
    __syncthreads();

    for (int s = tid; s < SDIM; s += 256)
        alpha[b * SDIM + s] *= inv;
}

// ---------------------------------------------------------------------------
// K4: cbar[b,i] = sum_s alpha[b,s] * context[b,s,i]
// ---------------------------------------------------------------------------
__global__ void k4_cbar(const float* __restrict__ context,
                        const float* __restrict__ alpha) {
    __shared__ float sal[128];
    int b  = blockIdx.y;
    int s0 = blockIdx.x * 128;
    int i  = threadIdx.x;
    if (i < 128) sal[i] = alpha[b * SDIM + s0 + i];
    __syncthreads();
    const float* cp = context + (size_t)b * SDIM * IDIM + (size_t)s0 * IDIM + i;
    float acc = 0.0f;
    #pragma unroll 4
    for (int s = 0; s < 128; s++) acc += sal[s] * cp[(size_t)s * IDIM];
    atomicAdd(&g_cbar[b * IDIM + i], acc);
}

// ---------------------------------------------------------------------------
// K5: hidden = Wc @ cbar + bc  (coalesced warp-per-row, 8-way split)
// ---------------------------------------------------------------------------
__global__ void __launch_bounds__(256) k5_out(const float* __restrict__ Wc,
                                              const float* __restrict__ bc,
                                              float* __restrict__ out) {
    __shared__ float sc[IDIM];
    int b  = blockIdx.x >> 3;
    int ho = (blockIdx.x & 7) * 64;
    int tid = threadIdx.x;
    int wid = tid >> 5, lane = tid & 31;

    sc[tid] = g_cbar[b * IDIM + tid];
    sc[tid + 256] = g_cbar[b * IDIM + tid + 256];
    __syncthreads();

    const float4* s4 = (const float4*)sc;
    #pragma unroll 1
    for (int r = wid; r < 64; r += 8) {
        int h = ho + r;
        const float4* w4 = (const float4*)(Wc + (size_t)h * IDIM);
        float acc = 0.0f;
        #pragma unroll
        for (int j = 0; j < 4; j++) {
            float4 w = w4[lane + 32 * j];
            float4 s = s4[lane + 32 * j];
            acc += w.x * s.x + w.y * s.y + w.z * s.z + w.w * s.w;
        }
        #pragma unroll
        for (int o = 16; o > 0; o >>= 1) acc += __shfl_xor_sync(0xffffffffu, acc, o);
        if (lane == 0) out[b * HDIM + h] = acc + bc[h];
    }
}

// ---------------------------------------------------------------------------
extern "C" void kernel_launch(void* const* d_in, const int* in_sizes, int n_in,
                              void* d_out, int out_size) {
    const float* inp          = (const float*)d_in[0];
    const float* context      = (const float*)d_in[1];
    const unsigned char* mraw = (const unsigned char*)d_in[2];
    const float* Wl           = (const float*)d_in[3];
    const float* bl           = (const float*)d_in[4];
    const float* Wc           = (const float*)d_in[5];
    const float* bc           = (const float*)d_in[6];
    const float* Vv           = (const float*)d_in[7];

    float* out    = (float*)d_out;
    float* hidden = out;                   // [B, HID]
    float* alpha  = out + BDIM * HDIM;     // [B, S]

    cudaFuncSetAttribute(k2_att_mma, cudaFuncAttributeMaxDynamicSharedMemorySize, SMEM_K2);

    k0_detect<<<1, 256>>>(mraw);
    int n4c = BDIM * SDIM * IDIM / 4;
    k_convA<<<n4c / 256, 256>>>(context, n4c);
    int n4w = HDIM * IDIM / 4;
    k_convB<<<n4w / 256, 256>>>(Wc, n4w);
    k1_hb<<<BDIM * 8, 256>>>(inp, Wl, bl, bc);
    k2_att_mma<<<BDIM * 16 * 4, 256, SMEM_K2>>>(Vv);
    k3_softmax<<<BDIM, 256>>>(mraw, alpha);
    k4_cbar<<<dim3(SDIM / 128, BDIM), 512>>>(context, alpha);
    k5_out<<<BDIM * 8, 256>>>(Wc, bc, hidden);
}

// round 16
// speedup vs baseline: 2.4618x; 1.0914x over previous
#include <cuda_runtime.h>
#include <cuda_fp16.h>
#include <math.h>
#include <stdint.h>

#define BDIM 64
#define SDIM 2048
#define IDIM 512
#define HDIM 512
#define BSCALE 512.0f
#define INV_BSCALE (1.0f / 512.0f)

// ---------------- device scratch (no cudaMalloc allowed) -------------------
__device__ float g_hb[BDIM * HDIM];
__device__ float g_att[BDIM * SDIM];
__device__ float g_cbar[BDIM * IDIM];
__device__ int   g_mask_is_byte;

__device__ __half g_ctx16[BDIM * SDIM * IDIM];   // fp16(ctx)
__device__ __half g_wc16 [HDIM * IDIM];          // fp16(512*Wc)

// ---------------- PTX helpers (sm_80-level only) ----------------------------
__device__ __forceinline__ uint32_t smem_u32(const void* p) {
    uint32_t a;
    asm("{ .reg .u64 t; cvta.to.shared.u64 t, %1; cvt.u32.u64 %0, t; }" : "=r"(a) : "l"(p));
    return a;
}
#define CP16(dst, src) asm volatile("cp.async.cg.shared.global [%0], [%1], 16;" :: "r"(dst), "l"(src))
#define CP_COMMIT()    asm volatile("cp.async.commit_group;" ::: "memory")
#define CP_WAIT(n)     asm volatile("cp.async.wait_group %0;" :: "n"(n) : "memory")

#define LDSM4(r, a)                                                           \
    asm volatile("ldmatrix.sync.aligned.m8n8.x4.shared.b16 {%0,%1,%2,%3}, [%4];" \
        : "=r"((r)[0]), "=r"((r)[1]), "=r"((r)[2]), "=r"((r)[3]) : "r"(a))

#define MMA_F16(c, a, b0, b1)                                                 \
    asm volatile("mma.sync.aligned.m16n8k16.row.col.f32.f16.f16.f32 "         \
        "{%0,%1,%2,%3},{%4,%5,%6,%7},{%8,%9},{%0,%1,%2,%3};"                  \
        : "+f"((c)[0]), "+f"((c)[1]), "+f"((c)[2]), "+f"((c)[3])              \
        : "r"((a)[0]), "r"((a)[1]), "r"((a)[2]), "r"((a)[3]), "r"(b0), "r"(b1))

// fast tanh: clamped exp form; abs err ~1e-6
__device__ __forceinline__ float fast_tanh(float x) {
    float xc = fminf(fmaxf(x, -10.0f), 10.0f);
    float e  = __expf(2.0f * xc);
    return __fdividef(e - 1.0f, e + 1.0f);
}

// ---------------------------------------------------------------------------
// K_front: fused convA | convB | k1 | k0 (all independent; one launch).
//   blocks [0, NBA)                : context fp32 -> fp16
//   blocks [NBA, NBA+NBB)          : Wc fp32 -> fp16(512*w)
//   blocks [NBA+NBB, NBA+NBB+NBK1) : hb = inp@Wl.T + bl + bc; zero scratch
//   last block                     : mask layout detect
// ---------------------------------------------------------------------------
#define NBA  (BDIM * SDIM * IDIM / 4 / 256)   // 8192
#define NBB  (HDIM * IDIM / 4 / 256)          // 256
#define NBK1 (BDIM * 8)                       // 512
#define NB_FRONT (NBA + NBB + NBK1 + 1)

__global__ void __launch_bounds__(256) k_front(const float* __restrict__ context,
                                               const float* __restrict__ Wc,
                                               const float* __restrict__ inp,
                                               const float* __restrict__ Wl,
                                               const float* __restrict__ bl,
                                               const float* __restrict__ bc,
                                               const unsigned char* __restrict__ mraw) {
    __shared__ float sin[IDIM];
    __shared__ int found;
    int bx = blockIdx.x;
    int tid = threadIdx.x;

    if (bx < NBA) {
        // convA
        int i = bx * 256 + tid;
        float4 v = ((const float4*)context)[i];
        __half2* hp = (__half2*)g_ctx16;
        hp[i * 2 + 0] = __halves2half2(__float2half_rn(v.x), __float2half_rn(v.y));
        hp[i * 2 + 1] = __halves2half2(__float2half_rn(v.z), __float2half_rn(v.w));
        return;
    }
    if (bx < NBA + NBB) {
        // convB
        int i = (bx - NBA) * 256 + tid;
        float4 v = ((const float4*)Wc)[i];
        __half2* hp = (__half2*)g_wc16;
        hp[i * 2 + 0] = __halves2half2(__float2half_rn(v.x * BSCALE), __float2half_rn(v.y * BSCALE));
        hp[i * 2 + 1] = __halves2half2(__float2half_rn(v.z * BSCALE), __float2half_rn(v.w * BSCALE));
        return;
    }
    if (bx < NBA + NBB + NBK1) {
        // k1: hb + zero scratch
        int kb = bx - NBA - NBB;
        int b  = kb >> 3;
        int ho = (kb & 7) * 64;
        int wid = tid >> 5, lane = tid & 31;

        sin[tid] = inp[b * IDIM + tid];
        sin[tid + 256] = inp[b * IDIM + tid + 256];
        g_att[b * SDIM + (kb & 7) * 256 + tid] = 0.0f;
        if (tid < 64) g_cbar[b * IDIM + ho + tid] = 0.0f;
        __syncthreads();

        const float4* s4 = (const float4*)sin;
        #pragma unroll 1
        for (int r = wid; r < 64; r += 8) {
            int h = ho + r;
            const float4* w4 = (const float4*)(Wl + (size_t)h * IDIM);
            float acc = 0.0f;
            #pragma unroll
            for (int j = 0; j < 4; j++) {
                float4 w = w4[lane + 32 * j];
                float4 s = s4[lane + 32 * j];
                acc += w.x * s.x + w.y * s.y + w.z * s.z + w.w * s.w;
            }
            #pragma unroll
            for (int o = 16; o > 0; o >>= 1) acc += __shfl_xor_sync(0xffffffffu, acc, o);
            if (lane == 0) g_hb[b * HDIM + h] = acc + bl[h] + bc[h];
        }
        return;
    }
    // k0: mask layout detect
    if (tid == 0) found = 0;
    __syncthreads();
    int acc = 0;
    for (int i = tid; i < 4096; i += 256)
        if ((i & 3) != 0 && mraw[i] != 0) acc = 1;
    if (acc) atomicOr(&found, 1);
    __syncthreads();
    if (tid == 0) g_mask_is_byte = found;
}

// ---------------------------------------------------------------------------
// K2: single-term fp16 GEMM + fast-tanh + V reduction.  (unchanged from R15)
// CTA tile 128(s) x 128(h); K=512 in 8 chunks of 64 (128B rows).
// Stage (32KB): A16 16K | B16 16K;  3 stages = 96KB -> 2 CTA/SM.
// ---------------------------------------------------------------------------
#define ST_A16 0u
#define ST_B16 16384u
#define STAGE_BYTES 32768u
#define NSTAGE 3
#define SMEM_K2 (NSTAGE * STAGE_BYTES)
#define NCHUNK 8

__global__ void __launch_bounds__(256, 2) k2_att_mma(const float* __restrict__ Vv) {
    extern __shared__ char smem[];
    __shared__ float sV[128], sHB[128], attred[128];
    uint32_t sb = smem_u32(smem);

    int tid  = threadIdx.x;
    int wid  = tid >> 5;
    int lane = tid & 31;
    int g    = lane >> 2;
    int tg   = lane & 3;
    int warp_m = wid & 1;
    int warp_n = wid >> 1;

    int bx = blockIdx.x;
    int b     = bx >> 6;
    int stile = (bx >> 2) & 15;
    int htile = bx & 3;
    int s0    = stile * 128;
    int hbase = htile * 128;
    int bb    = b * SDIM;

    if (tid < 128) {
        sV[tid]  = Vv[hbase + tid];
        sHB[tid] = g_hb[b * HDIM + hbase + tid];
        attred[tid] = 0.0f;
    }

    auto loadAB = [&](int kc, uint32_t stage_base) {
        int k0 = kc * 64;
        #pragma unroll
        for (int j = 0; j < 4; j++) {
            int idx = j * 256 + tid;
            int r = idx >> 3, c = idx & 7;
            uint32_t off = ((uint32_t)(r * 128 + c * 16)) ^ ((uint32_t)(r & 7) << 4);
            const __half* sA16 = g_ctx16 + (size_t)(bb + s0 + r) * IDIM + k0 + c * 8;
            const __half* sB16 = g_wc16 + (size_t)(hbase + r) * IDIM + k0 + c * 8;
            CP16(stage_base + ST_A16 + off, sA16);
            CP16(stage_base + ST_B16 + off, sB16);
        }
        CP_COMMIT();
    };

    int arow  = warp_m * 64 + (lane & 15);
    uint32_t akoff = (uint32_t)(lane & 16);
    uint32_t axor  = (uint32_t)((lane & 7) << 4);
    int brow  = (lane & 7) + ((lane & 16) >> 1);
    uint32_t bkoff = (uint32_t)(((lane >> 3) & 1) * 16);

    uint32_t offA[4], offB[2];
    #pragma unroll
    for (int t = 0; t < 4; t++) offA[t] = (uint32_t)((arow + t * 16) * 128) + akoff;
    #pragma unroll
    for (int p = 0; p < 2; p++) offB[p] = (uint32_t)((warp_n * 32 + p * 16 + brow) * 128) + bkoff;

    float acc[4][4][4];
    #pragma unroll
    for (int t = 0; t < 4; t++)
        #pragma unroll
        for (int n = 0; n < 4; n++)
            #pragma unroll
            for (int c = 0; c < 4; c++) acc[t][n][c] = 0.0f;

    loadAB(0, sb + 0u * STAGE_BYTES);
    loadAB(1, sb + 1u * STAGE_BYTES);

    #pragma unroll 1
    for (int i = 0; i < NCHUNK; i++) {
        if (i + 2 < NCHUNK)
            loadAB(i + 2, sb + (uint32_t)((i + 2) % NSTAGE) * STAGE_BYTES);
        if (i + 2 < NCHUNK)      { CP_WAIT(2); }
        else if (i + 1 < NCHUNK) { CP_WAIT(1); }
        else                     { CP_WAIT(0); }
        __syncthreads();

        uint32_t stb = sb + (uint32_t)(i % NSTAGE) * STAGE_BYTES;

        #pragma unroll
        for (int q = 0; q < 4; q++) {
            uint32_t qb = (uint32_t)(q * 32);
            uint32_t afr[4][4], bfr[2][4];
            #pragma unroll
            for (int t = 0; t < 4; t++)
                LDSM4(afr[t], stb + ST_A16 + ((offA[t] + qb) ^ axor));
            #pragma unroll
            for (int p = 0; p < 2; p++)
                LDSM4(bfr[p], stb + ST_B16 + ((offB[p] + qb) ^ axor));
            #pragma unroll
            for (int t = 0; t < 4; t++)
                #pragma unroll
                for (int nt = 0; nt < 4; nt++) {
                    int p = nt >> 1;
                    int r0 = (nt & 1) * 2;
                    MMA_F16(acc[t][nt], afr[t], bfr[p][r0], bfr[p][r0 + 1]);
                }
        }
        __syncthreads();
    }

    float rowsum[8];
    #pragma unroll
    for (int r = 0; r < 8; r++) rowsum[r] = 0.0f;
    #pragma unroll
    for (int t = 0; t < 4; t++) {
        #pragma unroll
        for (int nt = 0; nt < 4; nt++) {
            int hh = warp_n * 32 + nt * 8 + tg * 2;
            float v0 = sV[hh], v1 = sV[hh + 1];
            float h0 = sHB[hh], h1 = sHB[hh + 1];
            float* c = acc[t][nt];
            rowsum[t * 2 + 0] += v0 * fast_tanh(c[0] * INV_BSCALE + h0)
                               + v1 * fast_tanh(c[1] * INV_BSCALE + h1);
            rowsum[t * 2 + 1] += v0 * fast_tanh(c[2] * INV_BSCALE + h0)
                               + v1 * fast_tanh(c[3] * INV_BSCALE + h1);
        }
    }
    #pragma unroll
    for (int r = 0; r < 8; r++) {
        float s = rowsum[r];
        s += __shfl_xor_sync(0xffffffffu, s, 1);
        s += __shfl_xor_sync(0xffffffffu, s, 2);
        if (tg == 0) {
            int row = warp_m * 64 + (r >> 1) * 16 + (r & 1) * 8 + g;
            atomicAdd(&attred[row], s);
        }
    }
    __syncthreads();
    if (tid < 128) atomicAdd(&g_att[b * SDIM + s0 + tid], attred[tid]);
}

// ---------------------------------------------------------------------------
// K3: masked softmax over S per batch -> alpha
// ---------------------------------------------------------------------------
__device__ __forceinline__ bool mask_at(const unsigned char* m, int idx, int is_byte) {
    if (is_byte) return m[idx] != 0;
    return ((const int*)m)[idx] != 0;
}

__global__ void k3_softmax(const unsigned char* __restrict__ mraw,
                           float* __restrict__ alpha) {
    __shared__ float red[256];
    int b = blockIdx.x;
    int tid = threadIdx.x;
    int is_byte = g_mask_is_byte;
    const float NEG_INF = __int_as_float(0xff800000);

    float lmax = NEG_INF;
    for (int s = tid; s < SDIM; s += 256)
        if (!mask_at(mraw, b * SDIM + s, is_byte))
            lmax = fmaxf(lmax, g_att[b * SDIM + s]);
    red[tid] = lmax;
    __syncthreads();
    for (int o = 128; o > 0; o >>= 1) {
        if (tid < o) red[tid] = fmaxf(red[tid], red[tid + o]);
        __syncthreads();
    }
    float smax = red[0];
    __syncthreads();

    float lsum = 0.0f;
    for (int s = tid; s < SDIM; s += 256) {
        float e = 0.0f;
        if (!mask_at(mraw, b * SDIM + s, is_byte))
            e = expf(g_att[b * SDIM + s] - smax);
        alpha[b * SDIM + s] = e;
        lsum += e;
    }
    red[tid] = lsum;
    __syncthreads();
    for (int o = 128; o > 0; o >>= 1) {
        if (tid < o) red[tid] += red[tid + o];
        __syncthreads();
    }
    float inv = 1.0f / red[0];
    __syncthreads();

    for (int s = tid; s < SDIM; s += 256)
        alpha[b * SDIM + s] *= inv;
}

// ---------------------------------------------------------------------------
// K4: cbar[b,i] = sum_s alpha[b,s] * ctx16[b,s,i]  (fp16 context: half traffic)
// grid(S/128, B), block(256); each thread owns 2 adjacent columns via __half2.
// ---------------------------------------------------------------------------
__global__ void __launch_bounds__(256) k4_cbar(const float* __restrict__ alpha) {
    __shared__ float sal[128];
    int b  = blockIdx.y;
    int s0 = blockIdx.x * 128;
    int tid = threadIdx.x;
    if (tid < 128) sal[tid] = alpha[b * SDIM + s0 + tid];
    __syncthreads();
    const __half2* cp = (const __half2*)(g_ctx16 + (size_t)(b * SDIM + s0) * IDIM) + tid;
    float ax = 0.0f, ay = 0.0f;
    #pragma unroll 4
    for (int s = 0; s < 128; s++) {
        float2 v = __half22float2(cp[(size_t)s * (IDIM / 2)]);
        float a = sal[s];
        ax += a * v.x;
        ay += a * v.y;
    }
    atomicAdd(&g_cbar[b * IDIM + tid * 2 + 0], ax);
    atomicAdd(&g_cbar[b * IDIM + tid * 2 + 1], ay);
}

// ---------------------------------------------------------------------------
// K5: hidden = Wc @ cbar + bc  (coalesced warp-per-row, 8-way split)
// ---------------------------------------------------------------------------
__global__ void __launch_bounds__(256) k5_out(const float* __restrict__ Wc,
                                              const float* __restrict__ bc,
                                              float* __restrict__ out) {
    __shared__ float sc[IDIM];
    int b  = blockIdx.x >> 3;
    int ho = (blockIdx.x & 7) * 64;
    int tid = threadIdx.x;
    int wid = tid >> 5, lane = tid & 31;

    sc[tid] = g_cbar[b * IDIM + tid];
    sc[tid + 256] = g_cbar[b * IDIM + tid + 256];
    __syncthreads();

    const float4* s4 = (const float4*)sc;
    #pragma unroll 1
    for (int r = wid; r < 64; r += 8) {
        int h = ho + r;
        const float4* w4 = (const float4*)(Wc + (size_t)h * IDIM);
        float acc = 0.0f;
        #pragma unroll
        for (int j = 0; j < 4; j++) {
            float4 w = w4[lane + 32 * j];
            float4 s = s4[lane + 32 * j];
            acc += w.x * s.x + w.y * s.y + w.z * s.z + w.w * s.w;
        }
        #pragma unroll
        for (int o = 16; o > 0; o >>= 1) acc += __shfl_xor_sync(0xffffffffu, acc, o);
        if (lane == 0) out[b * HDIM + h] = acc + bc[h];
    }
}

// ---------------------------------------------------------------------------
extern "C" void kernel_launch(void* const* d_in, const int* in_sizes, int n_in,
                              void* d_out, int out_size) {
    const float* inp          = (const float*)d_in[0];
    const float* context      = (const float*)d_in[1];
    const unsigned char* mraw = (const unsigned char*)d_in[2];
    const float* Wl           = (const float*)d_in[3];
    const float* bl           = (const float*)d_in[4];
    const float* Wc           = (const float*)d_in[5];
    const float* bc           = (const float*)d_in[6];
    const float* Vv           = (const float*)d_in[7];

    float* out    = (float*)d_out;
    float* hidden = out;                   // [B, HID]
    float* alpha  = out + BDIM * HDIM;     // [B, S]

    cudaFuncSetAttribute(k2_att_mma, cudaFuncAttributeMaxDynamicSharedMemorySize, SMEM_K2);

    k_front<<<NB_FRONT, 256>>>(context, Wc, inp, Wl, bl, bc, mraw);
    k2_att_mma<<<BDIM * 16 * 4, 256, SMEM_K2>>>(Vv);
    k3_softmax<<<BDIM, 256>>>(mraw, alpha);
    k4_cbar<<<dim3(SDIM / 128, BDIM), 256>>>(alpha);
    k5_out<<<BDIM * 8, 256>>>(Wc, bc, hidden);
}

// round 17
// speedup vs baseline: 2.5151x; 1.0216x over previous
#include <cuda_runtime.h>
#include <cuda_fp16.h>
#include <math.h>
#include <stdint.h>

#define BDIM 64
#define SDIM 2048
#define IDIM 512
#define HDIM 512
#define BSCALE 512.0f
#define INV_BSCALE (1.0f / 512.0f)

// ---------------- device scratch (no cudaMalloc allowed) -------------------
__device__ float g_hb[BDIM * HDIM];
__device__ float g_att[BDIM * SDIM];
__device__ float g_cbar[BDIM * IDIM];
__device__ int   g_mask_is_byte;

__device__ __half g_ctx16[BDIM * SDIM * IDIM];   // fp16(ctx)
__device__ __half g_wc16 [HDIM * IDIM];          // fp16(512*Wc)

// ---------------- PTX helpers (sm_80-level only) ----------------------------
__device__ __forceinline__ uint32_t smem_u32(const void* p) {
    uint32_t a;
    asm("{ .reg .u64 t; cvta.to.shared.u64 t, %1; cvt.u32.u64 %0, t; }" : "=r"(a) : "l"(p));
    return a;
}
#define CP16(dst, src) asm volatile("cp.async.cg.shared.global [%0], [%1], 16;" :: "r"(dst), "l"(src))
#define CP_COMMIT()    asm volatile("cp.async.commit_group;" ::: "memory")
#define CP_WAIT(n)     asm volatile("cp.async.wait_group %0;" :: "n"(n) : "memory")

#define LDSM4(r, a)                                                           \
    asm volatile("ldmatrix.sync.aligned.m8n8.x4.shared.b16 {%0,%1,%2,%3}, [%4];" \
        : "=r"((r)[0]), "=r"((r)[1]), "=r"((r)[2]), "=r"((r)[3]) : "r"(a))

#define MMA_F16(c, a, b0, b1)                                                 \
    asm volatile("mma.sync.aligned.m16n8k16.row.col.f32.f16.f16.f32 "         \
        "{%0,%1,%2,%3},{%4,%5,%6,%7},{%8,%9},{%0,%1,%2,%3};"                  \
        : "+f"((c)[0]), "+f"((c)[1]), "+f"((c)[2]), "+f"((c)[3])              \
        : "r"((a)[0]), "r"((a)[1]), "r"((a)[2]), "r"((a)[3]), "r"(b0), "r"(b1))

// fast tanh: clamped exp form; abs err ~1e-6
__device__ __forceinline__ float fast_tanh(float x) {
    float xc = fminf(fmaxf(x, -10.0f), 10.0f);
    float e  = __expf(2.0f * xc);
    return __fdividef(e - 1.0f, e + 1.0f);
}

// ---------------------------------------------------------------------------
// K_front: fused convA | convB | k1 | k0 (all independent; one launch).
// ---------------------------------------------------------------------------
#define NBA  (BDIM * SDIM * IDIM / 4 / 256)   // 8192
#define NBB  (HDIM * IDIM / 4 / 256)          // 256
#define NBK1 (BDIM * 8)                       // 512
#define NB_FRONT (NBA + NBB + NBK1 + 1)

__global__ void __launch_bounds__(256) k_front(const float* __restrict__ context,
                                               const float* __restrict__ Wc,
                                               const float* __restrict__ inp,
                                               const float* __restrict__ Wl,
                                               const float* __restrict__ bl,
                                               const float* __restrict__ bc,
                                               const unsigned char* __restrict__ mraw) {
    __shared__ float sin[IDIM];
    __shared__ int found;
    int bx = blockIdx.x;
    int tid = threadIdx.x;

    if (bx < NBA) {
        int i = bx * 256 + tid;
        float4 v = ((const float4*)context)[i];
        __half2* hp = (__half2*)g_ctx16;
        hp[i * 2 + 0] = __halves2half2(__float2half_rn(v.x), __float2half_rn(v.y));
        hp[i * 2 + 1] = __halves2half2(__float2half_rn(v.z), __float2half_rn(v.w));
        return;
    }
    if (bx < NBA + NBB) {
        int i = (bx - NBA) * 256 + tid;
        float4 v = ((const float4*)Wc)[i];
        __half2* hp = (__half2*)g_wc16;
        hp[i * 2 + 0] = __halves2half2(__float2half_rn(v.x * BSCALE), __float2half_rn(v.y * BSCALE));
        hp[i * 2 + 1] = __halves2half2(__float2half_rn(v.z * BSCALE), __float2half_rn(v.w * BSCALE));
        return;
    }
    if (bx < NBA + NBB + NBK1) {
        int kb = bx - NBA - NBB;
        int b  = kb >> 3;
        int ho = (kb & 7) * 64;
        int wid = tid >> 5, lane = tid & 31;

        sin[tid] = inp[b * IDIM + tid];
        sin[tid + 256] = inp[b * IDIM + tid + 256];
        if (tid < 64) g_cbar[b * IDIM + ho + tid] = 0.0f;
        __syncthreads();

        const float4* s4 = (const float4*)sin;
        #pragma unroll 1
        for (int r = wid; r < 64; r += 8) {
            int h = ho + r;
            const float4* w4 = (const float4*)(Wl + (size_t)h * IDIM);
            float acc = 0.0f;
            #pragma unroll
            for (int j = 0; j < 4; j++) {
                float4 w = w4[lane + 32 * j];
                float4 s = s4[lane + 32 * j];
                acc += w.x * s.x + w.y * s.y + w.z * s.z + w.w * s.w;
            }
            #pragma unroll
            for (int o = 16; o > 0; o >>= 1) acc += __shfl_xor_sync(0xffffffffu, acc, o);
            if (lane == 0) g_hb[b * HDIM + h] = acc + bl[h] + bc[h];
        }
        // zero g_att
        g_att[b * SDIM + (kb & 7) * 256 + tid] = 0.0f;
        return;
    }
    // k0: mask layout detect
    if (tid == 0) found = 0;
    __syncthreads();
    int acc = 0;
    for (int i = tid; i < 4096; i += 256)
        if ((i & 3) != 0 && mraw[i] != 0) acc = 1;
    if (acc) atomicOr(&found, 1);
    __syncthreads();
    if (tid == 0) g_mask_is_byte = found;
}

// ---------------------------------------------------------------------------
// K2: single-term fp16 GEMM + fast-tanh + V reduction.
// Single __syncthreads per chunk: loadAB(i+2) issued AFTER the top barrier
// (barrier proves stage (i+2)%3's readers from iter i-1 are done; CP_WAIT(1)
// proves stage i%3's data has landed).
// CTA tile 128(s) x 128(h); K=512 in 8 chunks of 64 (128B rows).
// Stage (32KB): A16 16K | B16 16K;  3 stages = 96KB -> 2 CTA/SM.
// ---------------------------------------------------------------------------
#define ST_A16 0u
#define ST_B16 16384u
#define STAGE_BYTES 32768u
#define NSTAGE 3
#define SMEM_K2 (NSTAGE * STAGE_BYTES)
#define NCHUNK 8

__global__ void __launch_bounds__(256, 2) k2_att_mma(const float* __restrict__ Vv) {
    extern __shared__ char smem[];
    __shared__ float sV[128], sHB[128], attred[128];
    uint32_t sb = smem_u32(smem);

    int tid  = threadIdx.x;
    int wid  = tid >> 5;
    int lane = tid & 31;
    int g    = lane >> 2;
    int tg   = lane & 3;
    int warp_m = wid & 1;
    int warp_n = wid >> 1;

    int bx = blockIdx.x;
    int b     = bx >> 6;
    int stile = (bx >> 2) & 15;
    int htile = bx & 3;
    int s0    = stile * 128;
    int hbase = htile * 128;
    int bb    = b * SDIM;

    if (tid < 128) {
        sV[tid]  = Vv[hbase + tid];
        sHB[tid] = g_hb[b * HDIM + hbase + tid];
        attred[tid] = 0.0f;
    }

    auto loadAB = [&](int kc, uint32_t stage_base) {
        int k0 = kc * 64;
        #pragma unroll
        for (int j = 0; j < 4; j++) {
            int idx = j * 256 + tid;
            int r = idx >> 3, c = idx & 7;
            uint32_t off = ((uint32_t)(r * 128 + c * 16)) ^ ((uint32_t)(r & 7) << 4);
            const __half* sA16 = g_ctx16 + (size_t)(bb + s0 + r) * IDIM + k0 + c * 8;
            const __half* sB16 = g_wc16 + (size_t)(hbase + r) * IDIM + k0 + c * 8;
            CP16(stage_base + ST_A16 + off, sA16);
            CP16(stage_base + ST_B16 + off, sB16);
        }
        CP_COMMIT();
    };

    int arow  = warp_m * 64 + (lane & 15);
    uint32_t akoff = (uint32_t)(lane & 16);
    uint32_t axor  = (uint32_t)((lane & 7) << 4);
    int brow  = (lane & 7) + ((lane & 16) >> 1);
    uint32_t bkoff = (uint32_t)(((lane >> 3) & 1) * 16);

    uint32_t offA[4], offB[2];
    #pragma unroll
    for (int t = 0; t < 4; t++) offA[t] = (uint32_t)((arow + t * 16) * 128) + akoff;
    #pragma unroll
    for (int p = 0; p < 2; p++) offB[p] = (uint32_t)((warp_n * 32 + p * 16 + brow) * 128) + bkoff;

    float acc[4][4][4];
    #pragma unroll
    for (int t = 0; t < 4; t++)
        #pragma unroll
        for (int n = 0; n < 4; n++)
            #pragma unroll
            for (int c = 0; c < 4; c++) acc[t][n][c] = 0.0f;

    loadAB(0, sb + 0u * STAGE_BYTES);
    loadAB(1, sb + 1u * STAGE_BYTES);

    #pragma unroll 1
    for (int i = 0; i < NCHUNK; i++) {
        if (i + 1 < NCHUNK) { CP_WAIT(1); } else { CP_WAIT(0); }
        __syncthreads();
        if (i + 2 < NCHUNK)
            loadAB(i + 2, sb + (uint32_t)((i + 2) % NSTAGE) * STAGE_BYTES);

        uint32_t stb = sb + (uint32_t)(i % NSTAGE) * STAGE_BYTES;

        #pragma unroll
        for (int q = 0; q < 4; q++) {
            uint32_t qb = (uint32_t)(q * 32);
            uint32_t afr[4][4], bfr[2][4];
            #pragma unroll
            for (int t = 0; t < 4; t++)
                LDSM4(afr[t], stb + ST_A16 + ((offA[t] + qb) ^ axor));
            #pragma unroll
            for (int p = 0; p < 2; p++)
                LDSM4(bfr[p], stb + ST_B16 + ((offB[p] + qb) ^ axor));
            #pragma unroll
            for (int t = 0; t < 4; t++)
                #pragma unroll
                for (int nt = 0; nt < 4; nt++) {
                    int p = nt >> 1;
                    int r0 = (nt & 1) * 2;
                    MMA_F16(acc[t][nt], afr[t], bfr[p][r0], bfr[p][r0 + 1]);
                }
        }
    }

    float rowsum[8];
    #pragma unroll
    for (int r = 0; r < 8; r++) rowsum[r] = 0.0f;
    #pragma unroll
    for (int t = 0; t < 4; t++) {
        #pragma unroll
        for (int nt = 0; nt < 4; nt++) {
            int hh = warp_n * 32 + nt * 8 + tg * 2;
            float v0 = sV[hh], v1 = sV[hh + 1];
            float h0 = sHB[hh], h1 = sHB[hh + 1];
            float* c = acc[t][nt];
            rowsum[t * 2 + 0] += v0 * fast_tanh(c[0] * INV_BSCALE + h0)
                               + v1 * fast_tanh(c[1] * INV_BSCALE + h1);
            rowsum[t * 2 + 1] += v0 * fast_tanh(c[2] * INV_BSCALE + h0)
                               + v1 * fast_tanh(c[3] * INV_BSCALE + h1);
        }
    }
    #pragma unroll
    for (int r = 0; r < 8; r++) {
        float s = rowsum[r];
        s += __shfl_xor_sync(0xffffffffu, s, 1);
        s += __shfl_xor_sync(0xffffffffu, s, 2);
        if (tg == 0) {
            int row = warp_m * 64 + (r >> 1) * 16 + (r & 1) * 8 + g;
            atomicAdd(&attred[row], s);
        }
    }
    __syncthreads();
    if (tid < 128) atomicAdd(&g_att[b * SDIM + s0 + tid], attred[tid]);
}

// ---------------------------------------------------------------------------
// K3: masked softmax, single gmem pass (8 els/thread in registers)
// grid(B), block(256)
// ---------------------------------------------------------------------------
__device__ __forceinline__ bool mask_at(const unsigned char* m, int idx, int is_byte) {
    if (is_byte) return m[idx] != 0;
    return ((const int*)m)[idx] != 0;
}

__global__ void __launch_bounds__(256) k3_softmax(const unsigned char* __restrict__ mraw,
                                                  float* __restrict__ alpha) {
    __shared__ float red[256];
    int b = blockIdx.x;
    int tid = threadIdx.x;
    int is_byte = g_mask_is_byte;
    const float NEG_INF = __int_as_float(0xff800000);

    float a[8];
    bool msk[8];
    #pragma unroll
    for (int j = 0; j < 8; j++) {
        int s = j * 256 + tid;
        a[j]   = g_att[b * SDIM + s];
        msk[j] = mask_at(mraw, b * SDIM + s, is_byte);
    }

    float lmax = NEG_INF;
    #pragma unroll
    for (int j = 0; j < 8; j++) if (!msk[j]) lmax = fmaxf(lmax, a[j]);
    red[tid] = lmax;
    __syncthreads();
    for (int o = 128; o > 0; o >>= 1) {
        if (tid < o) red[tid] = fmaxf(red[tid], red[tid + o]);
        __syncthreads();
    }
    float smax = red[0];
    __syncthreads();

    float lsum = 0.0f;
    #pragma unroll
    for (int j = 0; j < 8; j++) {
        a[j] = msk[j] ? 0.0f : expf(a[j] - smax);
        lsum += a[j];
    }
    red[tid] = lsum;
    __syncthreads();
    for (int o = 128; o > 0; o >>= 1) {
        if (tid < o) red[tid] += red[tid + o];
        __syncthreads();
    }
    float inv = 1.0f / red[0];

    #pragma unroll
    for (int j = 0; j < 8; j++)
        alpha[b * SDIM + j * 256 + tid] = a[j] * inv;
}

// ---------------------------------------------------------------------------
// K4: cbar[b,i] = sum_s alpha[b,s] * ctx16[b,s,i]  (fp16 ctx, 16B loads)
// grid(S/128, B), block(512): c16 = tid&63 (16B col chunk), rgroup = tid>>6.
// Per-block smem reduce over 8 rgroups, then 1 atomic per column.
// ---------------------------------------------------------------------------
__global__ void __launch_bounds__(512) k4_cbar(const float* __restrict__ alpha) {
    __shared__ float sal[128];
    __shared__ float facc[8 * 512];
    int b  = blockIdx.y;
    int s0 = blockIdx.x * 128;
    int tid = threadIdx.x;
    int c16 = tid & 63;
    int rg  = tid >> 6;

    if (tid < 128) sal[tid] = alpha[b * SDIM + s0 + tid];
    __syncthreads();

    const uint4* base = (const uint4*)(g_ctx16 + (size_t)(b * SDIM + s0) * IDIM) + c16;
    float acc8[8];
    #pragma unroll
    for (int k = 0; k < 8; k++) acc8[k] = 0.0f;

    #pragma unroll 2
    for (int s = rg; s < 128; s += 8) {
        uint4 v = base[(size_t)s * 64];
        float a = sal[s];
        float2 f0 = __half22float2(*(__half2*)&v.x);
        float2 f1 = __half22float2(*(((__half2*)&v.x) + 1));
        float2 f2 = __half22float2(*(__half2*)&v.z);
        float2 f3 = __half22float2(*(((__half2*)&v.z) + 1));
        acc8[0] += a * f0.x; acc8[1] += a * f0.y;
        acc8[2] += a * f1.x; acc8[3] += a * f1.y;
        acc8[4] += a * f2.x; acc8[5] += a * f2.y;
        acc8[6] += a * f3.x; acc8[7] += a * f3.y;
    }
    #pragma unroll
    for (int k = 0; k < 8; k++) facc[rg * 512 + c16 * 8 + k] = acc8[k];
    __syncthreads();

    float s = 0.0f;
    #pragma unroll
    for (int r = 0; r < 8; r++) s += facc[r * 512 + tid];
    atomicAdd(&g_cbar[b * IDIM + tid], s);
}

// ---------------------------------------------------------------------------
// K5: hidden = Wc @ cbar + bc  (coalesced warp-per-row, 8-way split)
// ---------------------------------------------------------------------------
__global__ void __launch_bounds__(256) k5_out(const float* __restrict__ Wc,
                                              const float* __restrict__ bc,
                                              float* __restrict__ out) {
    __shared__ float sc[IDIM];
    int b  = blockIdx.x >> 3;
    int ho = (blockIdx.x & 7) * 64;
    int tid = threadIdx.x;
    int wid = tid >> 5, lane = tid & 31;

    sc[tid] = g_cbar[b * IDIM + tid];
    sc[tid + 256] = g_cbar[b * IDIM + tid + 256];
    __syncthreads();

    const float4* s4 = (const float4*)sc;
    #pragma unroll 1
    for (int r = wid; r < 64; r += 8) {
        int h = ho + r;
        const float4* w4 = (const float4*)(Wc + (size_t)h * IDIM);
        float acc = 0.0f;
        #pragma unroll
        for (int j = 0; j < 4; j++) {
            float4 w = w4[lane + 32 * j];
            float4 s = s4[lane + 32 * j];
            acc += w.x * s.x + w.y * s.y + w.z * s.z + w.w * s.w;
        }
        #pragma unroll
        for (int o = 16; o > 0; o >>= 1) acc += __shfl_xor_sync(0xffffffffu, acc, o);
        if (lane == 0) out[b * HDIM + h] = acc + bc[h];
    }
}

// ---------------------------------------------------------------------------
extern "C" void kernel_launch(void* const* d_in, const int* in_sizes, int n_in,
                              void* d_out, int out_size) {
    const float* inp          = (const float*)d_in[0];
    const float* context      = (const float*)d_in[1];
    const unsigned char* mraw = (const unsigned char*)d_in[2];
    const float* Wl           = (const float*)d_in[3];
    const float* bl           = (const float*)d_in[4];
    const float* Wc           = (const float*)d_in[5];
    const float* bc           = (const float*)d_in[6];
    const float* Vv           = (const float*)d_in[7];

    float* out    = (float*)d_out;
    float* hidden = out;                   // [B, HID]
    float* alpha  = out + BDIM * HDIM;     // [B, S]

    cudaFuncSetAttribute(k2_att_mma, cudaFuncAttributeMaxDynamicSharedMemorySize, SMEM_K2);

    k_front<<<NB_FRONT, 256>>>(context, Wc, inp, Wl, bl, bc, mraw);
    k2_att_mma<<<BDIM * 16 * 4, 256, SMEM_K2>>>(Vv);
    k3_softmax<<<BDIM, 256>>>(mraw, alpha);
    k4_cbar<<<dim3(SDIM / 128, BDIM), 512>>>(alpha);
    k5_out<<<BDIM * 8, 256>>>(Wc, bc, hidden);
}